// round 10
// baseline (speedup 1.0000x reference)
#include <cuda_runtime.h>
#include <cuda_bf16.h>
#include <cstdint>

#define THREADS 256
#define NCHUNK  256   // K = 8192, chunk = 32 fp32

__device__ __align__(256) float g_x32[128 * 8192];   // tf32-rounded x

__device__ __forceinline__ uint32_t smem_u32(const void* p) {
    uint32_t a;
    asm("{ .reg .u64 t; cvta.to.shared.u64 t, %1; cvt.u32.u64 %0, t; }" : "=r"(a) : "l"(p));
    return a;
}
__device__ __forceinline__ int sign_neg(int a, int b) {  // 1 if e_a*e_b negative
    int t = a >> 1, c = 0;
    while (t) { c += __popc(t & b); t >>= 1; }
    return c & 1;
}
__device__ __forceinline__ void ldsm4(uint32_t& r0, uint32_t& r1, uint32_t& r2, uint32_t& r3,
                                      uint32_t addr) {
    asm volatile("ldmatrix.sync.aligned.m8n8.x4.shared.b16 {%0,%1,%2,%3}, [%4];"
                 : "=r"(r0), "=r"(r1), "=r"(r2), "=r"(r3) : "r"(addr));
}
// a[] in ldsm matrix order {m0,m1,m2,m3}; mma wants {m0,m2,m1,m3}
__device__ __forceinline__ void mma_tf32(float* d, const uint32_t* a, const uint32_t* b) {
    asm volatile(
        "mma.sync.aligned.m16n8k8.row.col.f32.tf32.tf32.f32 "
        "{%0,%1,%2,%3}, {%4,%5,%6,%7}, {%8,%9}, {%0,%1,%2,%3};"
        : "+f"(d[0]), "+f"(d[1]), "+f"(d[2]), "+f"(d[3])
        : "r"(a[0]), "r"(a[2]), "r"(a[1]), "r"(a[3]), "r"(b[0]), "r"(b[1]));
}
__device__ __forceinline__ void cpasync16(uint32_t dst, const void* src) {
    asm volatile("cp.async.cg.shared.global [%0], [%1], 16;" :: "r"(dst), "l"(src) : "memory");
}
__device__ __forceinline__ uint32_t tf32u(float v) {
    uint32_t o;
    asm("cvt.rna.tf32.f32 %0, %1;" : "=r"(o) : "f"(v));
    return o;
}

// ---------- fp32 -> tf32-rounded fp32 (x only; w rounded in-kernel) ----------
__global__ void round_x(const float* __restrict__ src) {
    int i = blockIdx.x * blockDim.x + threadIdx.x;  // < 262144
    float4 v = reinterpret_cast<const float4*>(src)[i];
    uint4 o{tf32u(v.x), tf32u(v.y), tf32u(v.z), tf32u(v.w)};
    reinterpret_cast<uint4*>(g_x32)[i] = o;
}

// ---------- main GEMM: D[128 x 64] per CTA, K = 8192, tf32, chunk=32 ----------
__global__ void __launch_bounds__(THREADS, 1)
ga_gemm(const float* __restrict__ w, const float* __restrict__ bias,
        float* __restrict__ out) {
    // smem: A0[16K] A1[16K] B0[8K] B1[8K] = 48KB exactly (rows of 32 fp32 = 128B)
    __shared__ __align__(1024) uint8_t smem[49152];
    const int tid = threadIdx.x, wid = tid >> 5, lid = tid & 31, bx = blockIdx.x;
    const int wm = wid >> 1, wn = wid & 1;  // 4(M) x 2(N) warp grid, warp tile 32x32

    const uint32_t base = smem_u32(smem);
    const uint32_t sA[2] = {base, base + 16384};
    const uint32_t sB[2] = {base + 32768, base + 40960};

    // ---- B-build constants: thread -> row j = uu*16+kk, 8 dest elements ----
    const int j = tid >> 2, sub = tid & 3;
    const int kk = j & 15, uu = j >> 4;
    const int u = bx * 4 + uu;
    const int hsel = sub & 1, qsel = sub >> 1;
    const int kb01 = kk & 3, kb2 = (kk >> 2) & 1, kb3 = (kk >> 3) & 1;
    // source fp32-element offsets within the 32-wide chunk (blade bits 2-3 folded in)
    const int srcoff = 16 * qsel + 8 * (hsel ^ kb3);
    const int s0 = srcoff + 4 * (0 ^ kb2);
    const int s1 = srcoff + 4 * (1 ^ kb2);
    uint32_t msk[8];
#pragma unroll
    for (int e = 0; e < 8; e++) {
        int i = 8 * hsel + e;
        msk[e] = sign_neg(i, i ^ kk) ? 0x80000000u : 0u;
    }
    const uint32_t sts0 = (uint32_t)(j * 128 + ((2 * sub) ^ (j & 7)) * 16);
    const uint32_t sts1 = (uint32_t)(j * 128 + ((2 * sub + 1) ^ (j & 7)) * 16);
    const float* wbase = w + u * 8192;

    // ---- A cp.async addressing: 1024 x 16B blocks, 4 per thread ----
    int agoff[4];
    uint32_t aswz[4];
#pragma unroll
    for (int q = 0; q < 4; q++) {
        int idx = q * 256 + tid;
        int r = idx >> 3, blk = idx & 7;
        agoff[q] = r * 8192 + blk * 4;  // fp32 elements
        aswz[q] = (uint32_t)(r * 128 + (blk ^ (r & 7)) * 16);
    }

    // ---- ldmatrix address tables (buffer-relative) ----
    uint32_t aoff[2][4], boff[2][4];
#pragma unroll
    for (int mt = 0; mt < 2; mt++)
#pragma unroll
        for (int ks = 0; ks < 4; ks++) {
            int r = wm * 32 + mt * 16 + ((lid >> 4) & 1) * 8 + (lid & 7);
            int blk = 2 * ks + ((lid >> 3) & 1);
            aoff[mt][ks] = (uint32_t)(r * 128 + (blk ^ (r & 7)) * 16);
        }
#pragma unroll
    for (int g = 0; g < 2; g++)
#pragma unroll
        for (int ks = 0; ks < 4; ks++) {
            int n = wn * 32 + g * 16 + ((lid >> 4) & 1) * 8 + (lid & 7);
            int blk = 2 * ks + ((lid >> 3) & 1);
            boff[g][ks] = (uint32_t)(n * 128 + (blk ^ (n & 7)) * 16);
        }

    float d[2][4][4];
#pragma unroll
    for (int a = 0; a < 2; a++)
#pragma unroll
        for (int b = 0; b < 4; b++)
#pragma unroll
            for (int c = 0; c < 4; c++) d[a][b][c] = 0.f;

    // load w (raw fp32), tf32-round in registers
    uint4 V0, V1;
    auto load_w = [&](int koff) {
        float4 a = *reinterpret_cast<const float4*>(wbase + koff + s0);
        float4 b = *reinterpret_cast<const float4*>(wbase + koff + s1);
        V0 = make_uint4(tf32u(a.x), tf32u(a.y), tf32u(a.z), tf32u(a.w));
        V1 = make_uint4(tf32u(b.x), tf32u(b.y), tf32u(b.z), tf32u(b.w));
    };

    // ---- prologue: stage chunk 0 ----
#pragma unroll
    for (int q = 0; q < 4; q++) cpasync16(sA[0] + aswz[q], g_x32 + agoff[q]);
    asm volatile("cp.async.commit_group;" ::: "memory");
    load_w(0);

    for (int c = 0; c < NCHUNK; c++) {
        const int cur = c & 1;
        // ---- B tile (register-only deps): permute low blade bits + sign, store ----
        // WAR on this buffer is protected by the previous iteration's __syncthreads.
        {
            uint4 o0 = V0, o1 = V1;
            if (kb01 & 1) {  // swap adjacent elements
                uint32_t t;
                t = o0.x; o0.x = o0.y; o0.y = t;  t = o0.z; o0.z = o0.w; o0.w = t;
                t = o1.x; o1.x = o1.y; o1.y = t;  t = o1.z; o1.z = o1.w; o1.w = t;
            }
            if (kb01 & 2) {  // swap pairs
                uint32_t t;
                t = o0.x; o0.x = o0.z; o0.z = t;  t = o0.y; o0.y = o0.w; o0.w = t;
                t = o1.x; o1.x = o1.z; o1.z = t;  t = o1.y; o1.y = o1.w; o1.w = t;
            }
            o0.x ^= msk[0]; o0.y ^= msk[1]; o0.z ^= msk[2]; o0.w ^= msk[3];
            o1.x ^= msk[4]; o1.y ^= msk[5]; o1.z ^= msk[6]; o1.w ^= msk[7];
            uint8_t* bbuf = smem + 32768 + (cur << 13);
            *reinterpret_cast<uint4*>(bbuf + sts0) = o0;
            *reinterpret_cast<uint4*>(bbuf + sts1) = o1;
        }
        asm volatile("cp.async.wait_group 0;" ::: "memory");
        __syncthreads();
        // ---- prefetch chunk c+1 ----
        if (c + 1 < NCHUNK) {
            const int koffn = (c + 1) * 32;
#pragma unroll
            for (int q = 0; q < 4; q++)
                cpasync16(sA[cur ^ 1] + aswz[q], g_x32 + agoff[q] + koffn);
            asm volatile("cp.async.commit_group;" ::: "memory");
            load_w(koffn);
        }
        // ---- compute: 4 k-steps (k8 each) x (2 m-tiles x 4 n-tiles) ----
#pragma unroll
        for (int ks = 0; ks < 4; ks++) {
            uint32_t A0[4], A1[4], Bq0[4], Bq1[4];
            ldsm4(A0[0], A0[1], A0[2], A0[3], sA[cur] + aoff[0][ks]);
            ldsm4(A1[0], A1[1], A1[2], A1[3], sA[cur] + aoff[1][ks]);
            ldsm4(Bq0[0], Bq0[1], Bq0[2], Bq0[3], sB[cur] + boff[0][ks]);
            ldsm4(Bq1[0], Bq1[1], Bq1[2], Bq1[3], sB[cur] + boff[1][ks]);
            mma_tf32(d[0][0], A0, Bq0 + 0);
            mma_tf32(d[0][1], A0, Bq0 + 2);
            mma_tf32(d[0][2], A0, Bq1 + 0);
            mma_tf32(d[0][3], A0, Bq1 + 2);
            mma_tf32(d[1][0], A1, Bq0 + 0);
            mma_tf32(d[1][1], A1, Bq0 + 2);
            mma_tf32(d[1][2], A1, Bq1 + 0);
            mma_tf32(d[1][3], A1, Bq1 + 2);
        }
    }

    // ---- epilogue: D + bias -> out ----
#pragma unroll
    for (int mt = 0; mt < 2; mt++) {
        const int m0 = wm * 32 + mt * 16 + (lid >> 2);
#pragma unroll
        for (int nt = 0; nt < 4; nt++) {
            const int nc = bx * 64 + wn * 32 + nt * 8 + 2 * (lid & 3);
            const float2 bb = *reinterpret_cast<const float2*>(bias + nc);
            float2 v0{d[mt][nt][0] + bb.x, d[mt][nt][1] + bb.y};
            float2 v1{d[mt][nt][2] + bb.x, d[mt][nt][3] + bb.y};
            *reinterpret_cast<float2*>(out + (size_t)m0 * 8192 + nc) = v0;
            *reinterpret_cast<float2*>(out + (size_t)(m0 + 8) * 8192 + nc) = v1;
        }
    }
}

extern "C" void kernel_launch(void* const* d_in, const int* in_sizes, int n_in,
                              void* d_out, int out_size) {
    // Dispatch inputs by element count (robust to metadata ordering):
    //   x: 1048576, w: 4194304, b: 8192, cayley: 4096
    const float* x = nullptr;
    const float* w = nullptr;
    const float* bias = nullptr;
    for (int i = 0; i < n_in; i++) {
        if (in_sizes[i] == 1048576)      x    = (const float*)d_in[i];
        else if (in_sizes[i] == 4194304) w    = (const float*)d_in[i];
        else if (in_sizes[i] == 8192)    bias = (const float*)d_in[i];
    }
    float* out = (float*)d_out;

    round_x<<<1024, 256>>>(x);
    ga_gemm<<<128, THREADS>>>(w, bias, out);
}

// round 12
// speedup vs baseline: 1.2511x; 1.2511x over previous
#include <cuda_runtime.h>
#include <cuda_bf16.h>
#include <cstdint>

#define THREADS 256
#define NCHUNK  256   // K = 8192, chunk = 32 fp32

__device__ __align__(256) float g_x32[128 * 8192];   // tf32-rounded x

__device__ __forceinline__ uint32_t smem_u32(const void* p) {
    uint32_t a;
    asm("{ .reg .u64 t; cvta.to.shared.u64 t, %1; cvt.u32.u64 %0, t; }" : "=r"(a) : "l"(p));
    return a;
}
__device__ __forceinline__ int sign_neg(int a, int b) {  // 1 if e_a*e_b negative
    int t = a >> 1, c = 0;
    while (t) { c += __popc(t & b); t >>= 1; }
    return c & 1;
}
__device__ __forceinline__ void ldsm4(uint32_t& r0, uint32_t& r1, uint32_t& r2, uint32_t& r3,
                                      uint32_t addr) {
    asm volatile("ldmatrix.sync.aligned.m8n8.x4.shared.b16 {%0,%1,%2,%3}, [%4];"
                 : "=r"(r0), "=r"(r1), "=r"(r2), "=r"(r3) : "r"(addr));
}
// a[] in ldsm matrix order {m0,m1,m2,m3}; mma wants {m0,m2,m1,m3}
__device__ __forceinline__ void mma_tf32(float* d, const uint32_t* a, const uint32_t* b) {
    asm volatile(
        "mma.sync.aligned.m16n8k8.row.col.f32.tf32.tf32.f32 "
        "{%0,%1,%2,%3}, {%4,%5,%6,%7}, {%8,%9}, {%0,%1,%2,%3};"
        : "+f"(d[0]), "+f"(d[1]), "+f"(d[2]), "+f"(d[3])
        : "r"(a[0]), "r"(a[2]), "r"(a[1]), "r"(a[3]), "r"(b[0]), "r"(b[1]));
}
__device__ __forceinline__ void cpasync16(uint32_t dst, const void* src) {
    asm volatile("cp.async.cg.shared.global [%0], [%1], 16;" :: "r"(dst), "l"(src) : "memory");
}
__device__ __forceinline__ uint32_t tf32u(float v) {
    uint32_t o;
    asm("cvt.rna.tf32.f32 %0, %1;" : "=r"(o) : "f"(v));
    return o;
}
__device__ __forceinline__ uint32_t tf32b(uint32_t bits) {
    return tf32u(__uint_as_float(bits));
}

// ---------- fp32 -> tf32-rounded fp32 (x only; w rounded in-gemm) ----------
__global__ void round_x(const float* __restrict__ src) {
    int i = blockIdx.x * blockDim.x + threadIdx.x;  // < 262144
    float4 v = reinterpret_cast<const float4*>(src)[i];
    uint4 o{tf32u(v.x), tf32u(v.y), tf32u(v.z), tf32u(v.w)};
    reinterpret_cast<uint4*>(g_x32)[i] = o;
}

// ---------- main GEMM: D[128 x 64] per CTA, K = 8192, tf32, chunk=32 ----------
__global__ void __launch_bounds__(THREADS, 1)
ga_gemm(const float* __restrict__ w, const float* __restrict__ bias,
        float* __restrict__ out) {
    // smem: A0[16K] A1[16K] B0[8K] B1[8K] = 48KB exactly (rows of 32 fp32 = 128B)
    __shared__ __align__(1024) uint8_t smem[49152];
    const int tid = threadIdx.x, wid = tid >> 5, lid = tid & 31, bx = blockIdx.x;
    const int wm = wid >> 1, wn = wid & 1;  // 4(M) x 2(N) warp grid, warp tile 32x32

    const uint32_t base = smem_u32(smem);
    const uint32_t sA[2] = {base, base + 16384};
    const uint32_t sB[2] = {base + 32768, base + 40960};

    // ---- B-build constants: thread -> row j = uu*16+kk, 8 dest elements ----
    const int j = tid >> 2, sub = tid & 3;
    const int kk = j & 15, uu = j >> 4;
    const int u = bx * 4 + uu;
    const int hsel = sub & 1, qsel = sub >> 1;
    const int kb01 = kk & 3, kb2 = (kk >> 2) & 1, kb3 = (kk >> 3) & 1;
    // source fp32-element offsets within the 32-wide chunk (blade bits 2-3 folded in)
    const int srcoff = 16 * qsel + 8 * (hsel ^ kb3);
    const int s0 = srcoff + 4 * (0 ^ kb2);
    const int s1 = srcoff + 4 * (1 ^ kb2);
    uint32_t msk[8];
#pragma unroll
    for (int e = 0; e < 8; e++) {
        int i = 8 * hsel + e;
        msk[e] = sign_neg(i, i ^ kk) ? 0x80000000u : 0u;
    }
    const uint32_t sts0 = (uint32_t)(j * 128 + ((2 * sub) ^ (j & 7)) * 16);
    const uint32_t sts1 = (uint32_t)(j * 128 + ((2 * sub + 1) ^ (j & 7)) * 16);
    const float* wbase = w + u * 8192;

    // ---- A cp.async addressing: 1024 x 16B blocks, 4 per thread ----
    int agoff[4];
    uint32_t aswz[4];
#pragma unroll
    for (int q = 0; q < 4; q++) {
        int idx = q * 256 + tid;
        int r = idx >> 3, blk = idx & 7;
        agoff[q] = r * 8192 + blk * 4;  // fp32 elements
        aswz[q] = (uint32_t)(r * 128 + (blk ^ (r & 7)) * 16);
    }

    // ---- ldmatrix address tables (buffer-relative) ----
    uint32_t aoff[2][4], boff[2][4];
#pragma unroll
    for (int mt = 0; mt < 2; mt++)
#pragma unroll
        for (int ks = 0; ks < 4; ks++) {
            int r = wm * 32 + mt * 16 + ((lid >> 4) & 1) * 8 + (lid & 7);
            int blk = 2 * ks + ((lid >> 3) & 1);
            aoff[mt][ks] = (uint32_t)(r * 128 + (blk ^ (r & 7)) * 16);
        }
#pragma unroll
    for (int g = 0; g < 2; g++)
#pragma unroll
        for (int ks = 0; ks < 4; ks++) {
            int n = wn * 32 + g * 16 + ((lid >> 4) & 1) * 8 + (lid & 7);
            int blk = 2 * ks + ((lid >> 3) & 1);
            boff[g][ks] = (uint32_t)(n * 128 + (blk ^ (n & 7)) * 16);
        }

    float d[2][4][4];
#pragma unroll
    for (int a = 0; a < 2; a++)
#pragma unroll
        for (int b = 0; b < 4; b++)
#pragma unroll
            for (int c = 0; c < 4; c++) d[a][b][c] = 0.f;

    // load w RAW (bits only — no consumer until next iteration's B-build,
    // so the LDG latency hides under the compute phase)
    uint4 V0, V1;
    auto load_w = [&](int koff) {
        V0 = *reinterpret_cast<const uint4*>(wbase + koff + s0);
        V1 = *reinterpret_cast<const uint4*>(wbase + koff + s1);
    };

    // ---- prologue: stage chunk 0 ----
#pragma unroll
    for (int q = 0; q < 4; q++) cpasync16(sA[0] + aswz[q], g_x32 + agoff[q]);
    asm volatile("cp.async.commit_group;" ::: "memory");
    load_w(0);

    for (int c = 0; c < NCHUNK; c++) {
        const int cur = c & 1;
        asm volatile("cp.async.wait_group 0;" ::: "memory");
        // ---- B tile: tf32-round (deferred from prefetch), permute low blade bits,
        //      sign-XOR, store ----
        {
            uint4 o0, o1;
            o0.x = tf32b(V0.x); o0.y = tf32b(V0.y); o0.z = tf32b(V0.z); o0.w = tf32b(V0.w);
            o1.x = tf32b(V1.x); o1.y = tf32b(V1.y); o1.z = tf32b(V1.z); o1.w = tf32b(V1.w);
            if (kb01 & 1) {  // swap adjacent elements
                uint32_t t;
                t = o0.x; o0.x = o0.y; o0.y = t;  t = o0.z; o0.z = o0.w; o0.w = t;
                t = o1.x; o1.x = o1.y; o1.y = t;  t = o1.z; o1.z = o1.w; o1.w = t;
            }
            if (kb01 & 2) {  // swap pairs
                uint32_t t;
                t = o0.x; o0.x = o0.z; o0.z = t;  t = o0.y; o0.y = o0.w; o0.w = t;
                t = o1.x; o1.x = o1.z; o1.z = t;  t = o1.y; o1.y = o1.w; o1.w = t;
            }
            o0.x ^= msk[0]; o0.y ^= msk[1]; o0.z ^= msk[2]; o0.w ^= msk[3];
            o1.x ^= msk[4]; o1.y ^= msk[5]; o1.z ^= msk[6]; o1.w ^= msk[7];
            uint8_t* bbuf = smem + 32768 + (cur << 13);
            *reinterpret_cast<uint4*>(bbuf + sts0) = o0;
            *reinterpret_cast<uint4*>(bbuf + sts1) = o1;
        }
        __syncthreads();
        // ---- prefetch chunk c+1 ----
        if (c + 1 < NCHUNK) {
            const int koffn = (c + 1) * 32;
#pragma unroll
            for (int q = 0; q < 4; q++)
                cpasync16(sA[cur ^ 1] + aswz[q], g_x32 + agoff[q] + koffn);
            asm volatile("cp.async.commit_group;" ::: "memory");
            load_w(koffn);
        }
        // ---- compute: 4 k-steps (k8 each) x (2 m-tiles x 4 n-tiles) ----
#pragma unroll
        for (int ks = 0; ks < 4; ks++) {
            uint32_t A0[4], A1[4], Bq0[4], Bq1[4];
            ldsm4(A0[0], A0[1], A0[2], A0[3], sA[cur] + aoff[0][ks]);
            ldsm4(A1[0], A1[1], A1[2], A1[3], sA[cur] + aoff[1][ks]);
            ldsm4(Bq0[0], Bq0[1], Bq0[2], Bq0[3], sB[cur] + boff[0][ks]);
            ldsm4(Bq1[0], Bq1[1], Bq1[2], Bq1[3], sB[cur] + boff[1][ks]);
            mma_tf32(d[0][0], A0, Bq0 + 0);
            mma_tf32(d[0][1], A0, Bq0 + 2);
            mma_tf32(d[0][2], A0, Bq1 + 0);
            mma_tf32(d[0][3], A0, Bq1 + 2);
            mma_tf32(d[1][0], A1, Bq0 + 0);
            mma_tf32(d[1][1], A1, Bq0 + 2);
            mma_tf32(d[1][2], A1, Bq1 + 0);
            mma_tf32(d[1][3], A1, Bq1 + 2);
        }
    }

    // ---- epilogue: D + bias -> out ----
#pragma unroll
    for (int mt = 0; mt < 2; mt++) {
        const int m0 = wm * 32 + mt * 16 + (lid >> 2);
#pragma unroll
        for (int nt = 0; nt < 4; nt++) {
            const int nc = bx * 64 + wn * 32 + nt * 8 + 2 * (lid & 3);
            const float2 bb = *reinterpret_cast<const float2*>(bias + nc);
            float2 v0{d[mt][nt][0] + bb.x, d[mt][nt][1] + bb.y};
            float2 v1{d[mt][nt][2] + bb.x, d[mt][nt][3] + bb.y};
            *reinterpret_cast<float2*>(out + (size_t)m0 * 8192 + nc) = v0;
            *reinterpret_cast<float2*>(out + (size_t)(m0 + 8) * 8192 + nc) = v1;
        }
    }
}

extern "C" void kernel_launch(void* const* d_in, const int* in_sizes, int n_in,
                              void* d_out, int out_size) {
    // Dispatch inputs by element count (robust to metadata ordering):
    //   x: 1048576, w: 4194304, b: 8192, cayley: 4096
    const float* x = nullptr;
    const float* w = nullptr;
    const float* bias = nullptr;
    for (int i = 0; i < n_in; i++) {
        if (in_sizes[i] == 1048576)      x    = (const float*)d_in[i];
        else if (in_sizes[i] == 4194304) w    = (const float*)d_in[i];
        else if (in_sizes[i] == 8192)    bias = (const float*)d_in[i];
    }
    float* out = (float*)d_out;

    round_x<<<1024, 256>>>(x);
    ga_gemm<<<128, THREADS>>>(w, bias, out);
}

// round 13
// speedup vs baseline: 1.3544x; 1.0826x over previous
#include <cuda_runtime.h>
#include <cuda_bf16.h>
#include <cstdint>

#define THREADS 256
#define NCHUNK  128   // per-CTA K = 4096, chunk = 32 fp32 (split-K = 2)

__device__ __align__(256) float g_x32[128 * 8192];      // tf32-rounded x
__device__ __align__(256) float g_part[2 * 128 * 8192]; // split-K partials

__device__ __forceinline__ uint32_t smem_u32(const void* p) {
    uint32_t a;
    asm("{ .reg .u64 t; cvta.to.shared.u64 t, %1; cvt.u32.u64 %0, t; }" : "=r"(a) : "l"(p));
    return a;
}
__device__ __forceinline__ int sign_neg(int a, int b) {  // 1 if e_a*e_b negative
    int t = a >> 1, c = 0;
    while (t) { c += __popc(t & b); t >>= 1; }
    return c & 1;
}
__device__ __forceinline__ void ldsm4(uint32_t& r0, uint32_t& r1, uint32_t& r2, uint32_t& r3,
                                      uint32_t addr) {
    asm volatile("ldmatrix.sync.aligned.m8n8.x4.shared.b16 {%0,%1,%2,%3}, [%4];"
                 : "=r"(r0), "=r"(r1), "=r"(r2), "=r"(r3) : "r"(addr));
}
// a[] in ldsm matrix order {m0,m1,m2,m3}; mma wants {m0,m2,m1,m3}
__device__ __forceinline__ void mma_tf32(float* d, const uint32_t* a, const uint32_t* b) {
    asm volatile(
        "mma.sync.aligned.m16n8k8.row.col.f32.tf32.tf32.f32 "
        "{%0,%1,%2,%3}, {%4,%5,%6,%7}, {%8,%9}, {%0,%1,%2,%3};"
        : "+f"(d[0]), "+f"(d[1]), "+f"(d[2]), "+f"(d[3])
        : "r"(a[0]), "r"(a[2]), "r"(a[1]), "r"(a[3]), "r"(b[0]), "r"(b[1]));
}
__device__ __forceinline__ void cpasync16(uint32_t dst, const void* src) {
    asm volatile("cp.async.cg.shared.global [%0], [%1], 16;" :: "r"(dst), "l"(src) : "memory");
}
__device__ __forceinline__ uint32_t tf32u(float v) {
    uint32_t o;
    asm("cvt.rna.tf32.f32 %0, %1;" : "=r"(o) : "f"(v));
    return o;
}
__device__ __forceinline__ uint32_t tf32b(uint32_t bits) {
    return tf32u(__uint_as_float(bits));
}

// ---------- fp32 -> tf32-rounded fp32 (x only; w rounded in-gemm) ----------
__global__ void round_x(const float* __restrict__ src) {
    int i = blockIdx.x * blockDim.x + threadIdx.x;  // < 262144
    float4 v = reinterpret_cast<const float4*>(src)[i];
    uint4 o{tf32u(v.x), tf32u(v.y), tf32u(v.z), tf32u(v.w)};
    reinterpret_cast<uint4*>(g_x32)[i] = o;
}

// ---------- split-K reduce: out = p0 + p1 + bias ----------
__global__ void reduce_out(const float* __restrict__ bias, float* __restrict__ out) {
    int i = blockIdx.x * blockDim.x + threadIdx.x;  // < 262144 float4s
    float4 p0 = reinterpret_cast<const float4*>(g_part)[i];
    float4 p1 = reinterpret_cast<const float4*>(g_part + 1048576)[i];
    int col4 = i & 2047;  // (i*4) % 8192 / 4
    float4 bb = reinterpret_cast<const float4*>(bias)[col4];
    float4 o{p0.x + p1.x + bb.x, p0.y + p1.y + bb.y,
             p0.z + p1.z + bb.z, p0.w + p1.w + bb.w};
    reinterpret_cast<float4*>(out)[i] = o;
}

// ---------- main GEMM: D[128 x 64] per CTA, per-CTA K = 4096, tf32, chunk=32 ----------
__global__ void __launch_bounds__(THREADS, 2)
ga_gemm(const float* __restrict__ w) {
    // smem: A0[16K] A1[16K] B0[8K] B1[8K] = 48KB exactly (rows of 32 fp32 = 128B)
    __shared__ __align__(1024) uint8_t smem[49152];
    const int tid = threadIdx.x, wid = tid >> 5, lid = tid & 31;
    const int bx = blockIdx.x & 127, kh = blockIdx.x >> 7;
    const int wm = wid >> 1, wn = wid & 1;  // 4(M) x 2(N) warp grid, warp tile 32x32
    const int kbase = kh * 4096;

    const uint32_t base = smem_u32(smem);
    const uint32_t sA[2] = {base, base + 16384};
    const uint32_t sB[2] = {base + 32768, base + 40960};

    // ---- B-build constants: thread -> row j = uu*16+kk, 8 dest elements ----
    const int j = tid >> 2, sub = tid & 3;
    const int kk = j & 15, uu = j >> 4;
    const int u = bx * 4 + uu;
    const int hsel = sub & 1, qsel = sub >> 1;
    const int kb01 = kk & 3, kb2 = (kk >> 2) & 1, kb3 = (kk >> 3) & 1;
    // source fp32-element offsets within the 32-wide chunk (blade bits 2-3 folded in)
    const int srcoff = 16 * qsel + 8 * (hsel ^ kb3);
    const int s0 = srcoff + 4 * (0 ^ kb2);
    const int s1 = srcoff + 4 * (1 ^ kb2);
    uint32_t msk[8];
#pragma unroll
    for (int e = 0; e < 8; e++) {
        int i = 8 * hsel + e;
        msk[e] = sign_neg(i, i ^ kk) ? 0x80000000u : 0u;
    }
    const uint32_t sts0 = (uint32_t)(j * 128 + ((2 * sub) ^ (j & 7)) * 16);
    const uint32_t sts1 = (uint32_t)(j * 128 + ((2 * sub + 1) ^ (j & 7)) * 16);
    const float* wbase = w + u * 8192 + kbase;

    // ---- A cp.async addressing: 1024 x 16B blocks, 4 per thread ----
    int agoff[4];
    uint32_t aswz[4];
#pragma unroll
    for (int q = 0; q < 4; q++) {
        int idx = q * 256 + tid;
        int r = idx >> 3, blk = idx & 7;
        agoff[q] = r * 8192 + kbase + blk * 4;  // fp32 elements
        aswz[q] = (uint32_t)(r * 128 + (blk ^ (r & 7)) * 16);
    }

    // ---- ldmatrix address tables (buffer-relative) ----
    uint32_t aoff[2][4], boff[2][4];
#pragma unroll
    for (int mt = 0; mt < 2; mt++)
#pragma unroll
        for (int ks = 0; ks < 4; ks++) {
            int r = wm * 32 + mt * 16 + ((lid >> 4) & 1) * 8 + (lid & 7);
            int blk = 2 * ks + ((lid >> 3) & 1);
            aoff[mt][ks] = (uint32_t)(r * 128 + (blk ^ (r & 7)) * 16);
        }
#pragma unroll
    for (int g = 0; g < 2; g++)
#pragma unroll
        for (int ks = 0; ks < 4; ks++) {
            int n = wn * 32 + g * 16 + ((lid >> 4) & 1) * 8 + (lid & 7);
            int blk = 2 * ks + ((lid >> 3) & 1);
            boff[g][ks] = (uint32_t)(n * 128 + (blk ^ (n & 7)) * 16);
        }

    float d[2][4][4];
#pragma unroll
    for (int a = 0; a < 2; a++)
#pragma unroll
        for (int b = 0; b < 4; b++)
#pragma unroll
            for (int c = 0; c < 4; c++) d[a][b][c] = 0.f;

    // load w RAW (bits only — no consumer until next iteration's B-build,
    // so the LDG latency hides under the compute phase)
    uint4 V0, V1;
    auto load_w = [&](int koff) {
        V0 = *reinterpret_cast<const uint4*>(wbase + koff + s0);
        V1 = *reinterpret_cast<const uint4*>(wbase + koff + s1);
    };

    // ---- prologue: stage chunk 0 ----
#pragma unroll
    for (int q = 0; q < 4; q++) cpasync16(sA[0] + aswz[q], g_x32 + agoff[q]);
    asm volatile("cp.async.commit_group;" ::: "memory");
    load_w(0);

    for (int c = 0; c < NCHUNK; c++) {
        const int cur = c & 1;
        asm volatile("cp.async.wait_group 0;" ::: "memory");
        // ---- B tile: tf32-round (deferred), permute low blade bits, sign-XOR, store ----
        {
            uint4 o0, o1;
            o0.x = tf32b(V0.x); o0.y = tf32b(V0.y); o0.z = tf32b(V0.z); o0.w = tf32b(V0.w);
            o1.x = tf32b(V1.x); o1.y = tf32b(V1.y); o1.z = tf32b(V1.z); o1.w = tf32b(V1.w);
            if (kb01 & 1) {  // swap adjacent elements
                uint32_t t;
                t = o0.x; o0.x = o0.y; o0.y = t;  t = o0.z; o0.z = o0.w; o0.w = t;
                t = o1.x; o1.x = o1.y; o1.y = t;  t = o1.z; o1.z = o1.w; o1.w = t;
            }
            if (kb01 & 2) {  // swap pairs
                uint32_t t;
                t = o0.x; o0.x = o0.z; o0.z = t;  t = o0.y; o0.y = o0.w; o0.w = t;
                t = o1.x; o1.x = o1.z; o1.z = t;  t = o1.y; o1.y = o1.w; o1.w = t;
            }
            o0.x ^= msk[0]; o0.y ^= msk[1]; o0.z ^= msk[2]; o0.w ^= msk[3];
            o1.x ^= msk[4]; o1.y ^= msk[5]; o1.z ^= msk[6]; o1.w ^= msk[7];
            uint8_t* bbuf = smem + 32768 + (cur << 13);
            *reinterpret_cast<uint4*>(bbuf + sts0) = o0;
            *reinterpret_cast<uint4*>(bbuf + sts1) = o1;
        }
        __syncthreads();
        // ---- prefetch chunk c+1 ----
        if (c + 1 < NCHUNK) {
            const int koffn = (c + 1) * 32;
#pragma unroll
            for (int q = 0; q < 4; q++)
                cpasync16(sA[cur ^ 1] + aswz[q], g_x32 + agoff[q] + koffn);
            asm volatile("cp.async.commit_group;" ::: "memory");
            load_w(koffn);
        }
        // ---- compute: 4 k-steps (k8 each) x (2 m-tiles x 4 n-tiles) ----
#pragma unroll
        for (int ks = 0; ks < 4; ks++) {
            uint32_t A0[4], A1[4], Bq0[4], Bq1[4];
            ldsm4(A0[0], A0[1], A0[2], A0[3], sA[cur] + aoff[0][ks]);
            ldsm4(A1[0], A1[1], A1[2], A1[3], sA[cur] + aoff[1][ks]);
            ldsm4(Bq0[0], Bq0[1], Bq0[2], Bq0[3], sB[cur] + boff[0][ks]);
            ldsm4(Bq1[0], Bq1[1], Bq1[2], Bq1[3], sB[cur] + boff[1][ks]);
            mma_tf32(d[0][0], A0, Bq0 + 0);
            mma_tf32(d[0][1], A0, Bq0 + 2);
            mma_tf32(d[0][2], A0, Bq1 + 0);
            mma_tf32(d[0][3], A0, Bq1 + 2);
            mma_tf32(d[1][0], A1, Bq0 + 0);
            mma_tf32(d[1][1], A1, Bq0 + 2);
            mma_tf32(d[1][2], A1, Bq1 + 0);
            mma_tf32(d[1][3], A1, Bq1 + 2);
        }
    }

    // ---- epilogue: partial D -> g_part[kh] (bias added in reduce) ----
    float* pout = g_part + (size_t)kh * 1048576;
#pragma unroll
    for (int mt = 0; mt < 2; mt++) {
        const int m0 = wm * 32 + mt * 16 + (lid >> 2);
#pragma unroll
        for (int nt = 0; nt < 4; nt++) {
            const int nc = bx * 64 + wn * 32 + nt * 8 + 2 * (lid & 3);
            float2 v0{d[mt][nt][0], d[mt][nt][1]};
            float2 v1{d[mt][nt][2], d[mt][nt][3]};
            *reinterpret_cast<float2*>(pout + (size_t)m0 * 8192 + nc) = v0;
            *reinterpret_cast<float2*>(pout + (size_t)(m0 + 8) * 8192 + nc) = v1;
        }
    }
}

extern "C" void kernel_launch(void* const* d_in, const int* in_sizes, int n_in,
                              void* d_out, int out_size) {
    // Dispatch inputs by element count (robust to metadata ordering):
    //   x: 1048576, w: 4194304, b: 8192, cayley: 4096
    const float* x = nullptr;
    const float* w = nullptr;
    const float* bias = nullptr;
    for (int i = 0; i < n_in; i++) {
        if (in_sizes[i] == 1048576)      x    = (const float*)d_in[i];
        else if (in_sizes[i] == 4194304) w    = (const float*)d_in[i];
        else if (in_sizes[i] == 8192)    bias = (const float*)d_in[i];
    }
    float* out = (float*)d_out;

    round_x<<<1024, 256>>>(x);
    ga_gemm<<<256, THREADS>>>(w);
    reduce_out<<<1024, 256>>>(bias, out);
}